// round 15
// baseline (speedup 1.0000x reference)
#include <cuda_runtime.h>
#include <cuda_bf16.h>
#include <cuda_fp16.h>
#include <math.h>
#include <stdint.h>

// Problem constants
#define B_ROWS 131072
#define FEAT 256
#define LATD 128
#define NIN 640           // 2*FEAT + LATD
#define HG 32
#define HID 512
#define NE 3

// ---------------------------------------------------------------------------
// Scratch (device globals — no runtime allocation allowed)
// ---------------------------------------------------------------------------
__device__ float g_gate[(size_t)B_ROWS * NE];

__device__ __half g_x[(size_t)B_ROWS * NIN];
__device__ __half g_h1[(size_t)B_ROWS * HID];
__device__ __half g_h2[(size_t)B_ROWS * HID];

__device__ __half g_w1[NE * HID * NIN];
__device__ __half g_w2[NE * HID * HID];
__device__ __half g_w3[NE * HID * HID];
__device__ __half g_w4[NE * LATD * HID];

// ---------------------------------------------------------------------------
// helpers
// ---------------------------------------------------------------------------
__device__ __forceinline__ uint32_t smem_u32(const void* p) {
    uint32_t a;
    asm("{ .reg .u64 t; cvta.to.shared.u64 t, %1; cvt.u32.u64 %0, t; }" : "=r"(a) : "l"(p));
    return a;
}

#define CP_ASYNC16(dst, src) \
    asm volatile("cp.async.cg.shared.global [%0], [%1], 16;" :: "r"(dst), "l"(src))
#define CP_COMMIT() asm volatile("cp.async.commit_group;" ::: "memory")
#define CP_WAIT0()  asm volatile("cp.async.wait_group 0;" ::: "memory")

__device__ __forceinline__ void mma16816h(float* c, const unsigned* a, const unsigned* b) {
    asm volatile(
        "mma.sync.aligned.m16n8k16.row.col.f32.f16.f16.f32 "
        "{%0,%1,%2,%3}, {%4,%5,%6,%7}, {%8,%9}, {%0,%1,%2,%3};\n"
        : "+f"(c[0]), "+f"(c[1]), "+f"(c[2]), "+f"(c[3])
        : "r"(a[0]), "r"(a[1]), "r"(a[2]), "r"(a[3]), "r"(b[0]), "r"(b[1]));
}

__device__ __forceinline__ unsigned lds32h(const __half* p) {
    return *reinterpret_cast<const unsigned*>(p);
}

// ---------------------------------------------------------------------------
// weight conversion — single launch for all four weight tensors
// ---------------------------------------------------------------------------
#define W1_N4 (NE * HID * NIN / 4)
#define W2_N4 (NE * HID * HID / 4)
#define W4_N4 (NE * LATD * HID / 4)
#define WTOT_N4 (W1_N4 + 2 * W2_N4 + W4_N4)

__global__ __launch_bounds__(256) void convert_all(
    const float* __restrict__ W1, const float* __restrict__ W2,
    const float* __restrict__ W3, const float* __restrict__ W4)
{
    int i = blockIdx.x * blockDim.x + threadIdx.x;
    if (i >= WTOT_N4) return;
    const float* src;
    __half* dst;
    int off;
    if (i < W1_N4)                    { src = W1; dst = g_w1; off = i; }
    else if (i < W1_N4 + W2_N4)       { src = W2; dst = g_w2; off = i - W1_N4; }
    else if (i < W1_N4 + 2 * W2_N4)   { src = W3; dst = g_w3; off = i - W1_N4 - W2_N4; }
    else                              { src = W4; dst = g_w4; off = i - W1_N4 - 2 * W2_N4; }
    float4 v = reinterpret_cast<const float4*>(src)[off];
    __half2* dp = reinterpret_cast<__half2*>(dst) + off * 2;
    dp[0] = __half2{__float2half_rn(v.x), __float2half_rn(v.y)};
    dp[1] = __half2{__float2half_rn(v.z), __float2half_rn(v.w)};
}

// ---------------------------------------------------------------------------
// fused prep: reads fp32 inputs ONCE; writes g_x (fp16) AND full gate path.
// ---------------------------------------------------------------------------
__global__ __launch_bounds__(256) void prep_gate_kernel(
    const float* __restrict__ f1, const float* __restrict__ f2,
    const float* __restrict__ lat,
    const float* __restrict__ g0w, const float* __restrict__ g0b,
    const float* __restrict__ g1w, const float* __restrict__ g1b,
    const float* __restrict__ g2w, const float* __restrict__ g2b,
    float* __restrict__ out_gate)
{
    __shared__ float As[16][260];
    __shared__ float Ws[16][36];
    __shared__ float us[256][33];
    __shared__ float w1s[32][33];
    __shared__ float b1s[32];
    __shared__ float w2s[3][32];
    __shared__ float b2s[3];

    const int tid = threadIdx.x;
    const int tx = tid & 7;
    const int ty = tid >> 3;
    const int m0 = blockIdx.x * 256;

    for (int idx = tid; idx < 32 * 32; idx += 256)
        w1s[idx >> 5][idx & 31] = g1w[idx];
    if (tid < 32) b1s[tid] = g1b[tid];
    if (tid < 96) w2s[tid / 32][tid % 32] = g2w[tid];
    if (tid < 3) b2s[tid] = g2b[tid];

    float acc[8][4];
#pragma unroll
    for (int i = 0; i < 8; ++i)
#pragma unroll
        for (int j = 0; j < 4; ++j) acc[i][j] = 0.f;

    for (int k0 = 0; k0 < NIN; k0 += 16) {
#pragma unroll
        for (int r = 0; r < 4; ++r) {
            int idx = r * 256 + tid;
            int m = idx >> 2;
            int kq = (idx & 3) * 4;
            int kg = k0 + kq;
            float4 v;
            if (kg < FEAT)
                v = *reinterpret_cast<const float4*>(&f1[(size_t)(m0 + m) * FEAT + kg]);
            else if (kg < 2 * FEAT)
                v = *reinterpret_cast<const float4*>(&f2[(size_t)(m0 + m) * FEAT + (kg - FEAT)]);
            else
                v = *reinterpret_cast<const float4*>(&lat[(size_t)(m0 + m) * LATD + (kg - 2 * FEAT)]);
            As[kq + 0][m] = v.x; As[kq + 1][m] = v.y;
            As[kq + 2][m] = v.z; As[kq + 3][m] = v.w;
            __half2 h01 = __half2{__float2half_rn(v.x), __float2half_rn(v.y)};
            __half2 h23 = __half2{__float2half_rn(v.z), __float2half_rn(v.w)};
            size_t xb = (size_t)(m0 + m) * NIN + kg;
            *reinterpret_cast<__half2*>(&g_x[xb])     = h01;
            *reinterpret_cast<__half2*>(&g_x[xb + 2]) = h23;
        }
        if (tid < 128) {
            int n = tid >> 2;
            int kq = (tid & 3) * 4;
            float4 v = *reinterpret_cast<const float4*>(&g0w[(size_t)n * NIN + k0 + kq]);
            Ws[kq + 0][n] = v.x; Ws[kq + 1][n] = v.y;
            Ws[kq + 2][n] = v.z; Ws[kq + 3][n] = v.w;
        }
        __syncthreads();
#pragma unroll
        for (int k = 0; k < 16; ++k) {
            const float4 a0 = *reinterpret_cast<const float4*>(&As[k][ty * 8]);
            const float4 a1 = *reinterpret_cast<const float4*>(&As[k][ty * 8 + 4]);
            const float4 b  = *reinterpret_cast<const float4*>(&Ws[k][tx * 4]);
            float av[8] = {a0.x, a0.y, a0.z, a0.w, a1.x, a1.y, a1.z, a1.w};
            float bv[4] = {b.x, b.y, b.z, b.w};
#pragma unroll
            for (int i = 0; i < 8; ++i)
#pragma unroll
                for (int j = 0; j < 4; ++j)
                    acc[i][j] = fmaf(av[i], bv[j], acc[i][j]);
        }
        __syncthreads();
    }

    float bb[4];
#pragma unroll
    for (int j = 0; j < 4; ++j) bb[j] = g0b[tx * 4 + j];
#pragma unroll
    for (int i = 0; i < 8; ++i)
#pragma unroll
        for (int j = 0; j < 4; ++j)
            us[ty * 8 + i][tx * 4 + j] = acc[i][j] + bb[j];
    __syncthreads();

    const int m = m0 + tid;

    float eu[32];
#pragma unroll
    for (int k = 0; k < 32; ++k) {
        float x = us[tid][k];
        eu[k] = (x > 0.f) ? x : expm1f(x);
    }
    float ev[32];
#pragma unroll
    for (int j = 0; j < 32; ++j) {
        float v = b1s[j];
#pragma unroll
        for (int k = 0; k < 32; ++k) v = fmaf(eu[k], w1s[j][k], v);
        ev[j] = (v > 0.f) ? v : expm1f(v);
    }
    float s[3];
#pragma unroll
    for (int e = 0; e < 3; ++e) {
        float v = b2s[e];
#pragma unroll
        for (int j = 0; j < 32; ++j) v = fmaf(ev[j], w2s[e][j], v);
        s[e] = v;
    }
    float mx = fmaxf(s[0], fmaxf(s[1], s[2]));
    float p0 = expf(s[0] - mx);
    float p1 = expf(s[1] - mx);
    float p2 = expf(s[2] - mx);
    float inv = 1.f / (p0 + p1 + p2);
    p0 *= inv; p1 *= inv; p2 *= inv;

    g_gate[(size_t)m * 3 + 0] = p0;
    g_gate[(size_t)m * 3 + 1] = p1;
    g_gate[(size_t)m * 3 + 2] = p2;
    out_gate[(size_t)m * 3 + 0] = p0;
    out_gate[(size_t)m * 3 + 1] = p1;
    out_gate[(size_t)m * 3 + 2] = p2;
}

// ---------------------------------------------------------------------------
// blend_mma v10: 384 threads (12 warps = 3/SMSP), tile M=128 x N=64 x E=3,
// warps split 2(M) x 2(N) x 3(expert): each warp owns a 64x32 sub-tile of ONE
// expert (acc 64 regs). Cross-expert gate-blend via smem reduction (3 phases).
// K-chunk 128, 2-stage cp.async pipeline, 1 CTA/SM.
// smem: 2 stages x (128+192)*136 halves (174080B) + 128x72 float sbuf (36864B)
// ---------------------------------------------------------------------------
#define ASTRIDE 136
#define AROWS 128
#define WROWS 192
#define STAGE_U ((AROWS + WROWS) * ASTRIDE)   // 43520 half units
#define SBSTRIDE 72
#define NTHREADS 384

template <int KDIM, int NOUT>
__device__ __forceinline__ void prefetch_chunk(
    __half* sm, int stage, int k0, int m0, int n0,
    const __half* __restrict__ A, const __half* __restrict__ W)
{
    const int tid = threadIdx.x;
    const uint32_t base = smem_u32(sm) + (uint32_t)stage * STAGE_U * 2;
    // A: 128 rows * 16 = 2048 chunks ; W: 192 rows * 16 = 3072 chunks; total 5120
#pragma unroll
    for (int it = 0; it < 14; ++it) {
        int i = tid + it * NTHREADS;
        if (i >= 5120) break;
        uint32_t dst;
        const __half* src;
        if (i < 2048) {
            int row = i >> 4, c = i & 15;
            src = A + (size_t)(m0 + row) * KDIM + k0 + c * 8;
            dst = base + (uint32_t)(row * ASTRIDE + c * 8) * 2;
        } else {
            int j = i - 2048;
            int r = j >> 4, c = j & 15;       // r in [0,192)
            int e = r >> 6, n = r & 63;
            src = W + ((size_t)e * NOUT + n0 + n) * KDIM + k0 + c * 8;
            dst = base + (uint32_t)(AROWS * ASTRIDE + r * ASTRIDE + c * 8) * 2;
        }
        CP_ASYNC16(dst, src);
    }
}

template <int KDIM, int NOUT, bool RELU, bool FP32OUT>
__global__ __launch_bounds__(NTHREADS, 1) void blend_mma(
    const __half* __restrict__ A, const __half* __restrict__ W,
    const float* __restrict__ bias,
    __half* __restrict__ Oh, float* __restrict__ Ofp)
{
    extern __shared__ __half smbuf[];
    float* sbuf = reinterpret_cast<float*>(smbuf + 2 * STAGE_U);  // [128][SBSTRIDE]

    constexpr int NTN = NOUT / 64;
    constexpr int NT = (B_ROWS / 128) * NTN;
    constexpr int NCH = KDIM / 128;

    const int tid = threadIdx.x;
    const int w = tid >> 5, lane = tid & 31;
    const int wm = w & 1;            // 2 along M (64 rows each)
    const int wn = (w >> 1) & 1;     // 2 along N (32 cols each)
    const int we = w >> 2;           // 3 experts
    const int g = lane >> 2, t = lane & 3;
    const int stride = gridDim.x;

    int tile = blockIdx.x;
    if (tile >= NT) return;

    {
        int m0 = (tile / NTN) * 128, n0 = (tile % NTN) * 64;
        prefetch_chunk<KDIM, NOUT>(smbuf, 0, 0, m0, n0, A, W);
        CP_COMMIT();
    }
    int gbuf = 0;

    while (tile < NT) {
        const int m0 = (tile / NTN) * 128;
        const int n0 = (tile % NTN) * 64;

        // this warp's gate values (its expert only), 4 mt x 2 h row groups
        float gv[4][2];
#pragma unroll
        for (int mt = 0; mt < 4; ++mt)
#pragma unroll
            for (int h = 0; h < 2; ++h) {
                int m = m0 + wm * 64 + mt * 16 + g + h * 8;
                gv[mt][h] = g_gate[(size_t)m * 3 + we];
            }
        // this warp's bias (its expert only), 4 nt col groups
        float bb[4][2];
#pragma unroll
        for (int nt = 0; nt < 4; ++nt) {
            int n = n0 + wn * 32 + nt * 8 + t * 2;
            bb[nt][0] = bias[we * NOUT + n];
            bb[nt][1] = bias[we * NOUT + n + 1];
        }

        float acc[4][4][4];
#pragma unroll
        for (int mt = 0; mt < 4; ++mt)
#pragma unroll
            for (int nt = 0; nt < 4; ++nt)
#pragma unroll
                for (int c = 0; c < 4; ++c) acc[mt][nt][c] = 0.f;

        for (int ch = 0; ch < NCH; ++ch) {
            CP_WAIT0();
            __syncthreads();

            {
                int pch = ch + 1, ptile = tile;
                if (pch >= NCH) { pch = 0; ptile += stride; }
                if (ptile < NT) {
                    int pm0 = (ptile / NTN) * 128, pn0 = (ptile % NTN) * 64;
                    prefetch_chunk<KDIM, NOUT>(smbuf, gbuf ^ 1, pch * 128,
                                               pm0, pn0, A, W);
                    CP_COMMIT();
                }
            }

            const __half* sA = smbuf + gbuf * STAGE_U;
            const __half* sW = sA + AROWS * ASTRIDE;

#pragma unroll
            for (int ks = 0; ks < 128; ks += 16) {
                unsigned a[4][4];
#pragma unroll
                for (int mt = 0; mt < 4; ++mt) {
                    int r0 = (wm * 64 + mt * 16 + g) * ASTRIDE + ks + t * 2;
                    int r1 = r0 + 8 * ASTRIDE;
                    a[mt][0] = lds32h(sA + r0);
                    a[mt][1] = lds32h(sA + r1);
                    a[mt][2] = lds32h(sA + r0 + 8);
                    a[mt][3] = lds32h(sA + r1 + 8);
                }
                unsigned b[4][2];
#pragma unroll
                for (int nt = 0; nt < 4; ++nt) {
                    int c0 = (we * 64 + wn * 32 + nt * 8 + g) * ASTRIDE + ks + t * 2;
                    b[nt][0] = lds32h(sW + c0);
                    b[nt][1] = lds32h(sW + c0 + 8);
                }
#pragma unroll
                for (int mt = 0; mt < 4; ++mt)
#pragma unroll
                    for (int nt = 0; nt < 4; ++nt)
                        mma16816h(acc[mt][nt], a[mt], b[nt]);
            }
            gbuf ^= 1;
        }

        // ---------------- cross-expert epilogue reduction ----------------
        // val = gate_we * (acc + bias_we); sum over experts via sbuf phases.
#pragma unroll
        for (int phase = 0; phase < 3; ++phase) {
            if (we == phase) {
#pragma unroll
                for (int mt = 0; mt < 4; ++mt)
#pragma unroll
                    for (int h = 0; h < 2; ++h) {
                        int row = wm * 64 + mt * 16 + g + h * 8;
#pragma unroll
                        for (int nt = 0; nt < 4; ++nt) {
                            int col = wn * 32 + nt * 8 + t * 2;
                            float v0 = gv[mt][h] * (acc[mt][nt][h * 2 + 0] + bb[nt][0]);
                            float v1 = gv[mt][h] * (acc[mt][nt][h * 2 + 1] + bb[nt][1]);
                            float* sp = &sbuf[row * SBSTRIDE + col];
                            if (phase == 0) {
                                sp[0] = v0; sp[1] = v1;
                            } else if (phase == 1) {
                                sp[0] += v0; sp[1] += v1;
                            } else {
                                // final: add, activate, store to gmem
                                float o0 = sp[0] + v0, o1 = sp[1] + v1;
                                if (RELU) { o0 = fmaxf(o0, 0.f); o1 = fmaxf(o1, 0.f); }
                                int m = m0 + row, n = n0 + col;
                                if (FP32OUT) {
                                    float2 o = {o0, o1};
                                    *reinterpret_cast<float2*>(&Ofp[(size_t)m * NOUT + n]) = o;
                                } else {
                                    *reinterpret_cast<__half2*>(&Oh[(size_t)m * NOUT + n]) =
                                        __half2{__float2half_rn(o0), __float2half_rn(o1)};
                                }
                            }
                        }
                    }
            }
            if (phase < 2) __syncthreads();
        }

        tile += stride;
    }
}

// ---------------------------------------------------------------------------
// Launch
// ---------------------------------------------------------------------------
extern "C" void kernel_launch(void* const* d_in, const int* in_sizes, int n_in,
                              void* d_out, int out_size)
{
    const float* f1  = (const float*)d_in[0];
    const float* f2  = (const float*)d_in[1];
    const float* lat = (const float*)d_in[2];
    const float* g0w = (const float*)d_in[3];
    const float* g0b = (const float*)d_in[4];
    const float* g1w = (const float*)d_in[5];
    const float* g1b = (const float*)d_in[6];
    const float* g2w = (const float*)d_in[7];
    const float* g2b = (const float*)d_in[8];
    const float* W1  = (const float*)d_in[9];
    const float* b1  = (const float*)d_in[10];
    const float* W2  = (const float*)d_in[11];
    const float* b2  = (const float*)d_in[12];
    const float* W3  = (const float*)d_in[13];
    const float* b3  = (const float*)d_in[14];
    const float* W4  = (const float*)d_in[15];
    const float* b4  = (const float*)d_in[16];

    float* out      = (float*)d_out;
    float* gate_out = out + (size_t)B_ROWS * LATD;

    __half *w1, *w2, *w3, *w4, *x, *h1, *h2;
    cudaGetSymbolAddress((void**)&w1, g_w1);
    cudaGetSymbolAddress((void**)&w2, g_w2);
    cudaGetSymbolAddress((void**)&w3, g_w3);
    cudaGetSymbolAddress((void**)&w4, g_w4);
    cudaGetSymbolAddress((void**)&x,  g_x);
    cudaGetSymbolAddress((void**)&h1, g_h1);
    cudaGetSymbolAddress((void**)&h2, g_h2);

    int nsm = 148;
    cudaDeviceGetAttribute(&nsm, cudaDevAttrMultiProcessorCount, 0);

    // single-launch weight conversion
    convert_all<<<(WTOT_N4 + 255) / 256, 256>>>(W1, W2, W3, W4);

    // fused prep: inputs -> g_x + full gate path
    prep_gate_kernel<<<B_ROWS / 256, 256>>>(f1, f2, lat, g0w, g0b,
                                            g1w, g1b, g2w, g2b, gate_out);

    // blend layers — persistent grid, smem = 2 stages + reduction buffer
    constexpr int SMEM_BYTES = 2 * STAGE_U * 2 + 128 * SBSTRIDE * 4;  // 210944

    cudaFuncSetAttribute(blend_mma<NIN, HID, true, false>,
                         cudaFuncAttributeMaxDynamicSharedMemorySize, SMEM_BYTES);
    cudaFuncSetAttribute(blend_mma<HID, HID, true, false>,
                         cudaFuncAttributeMaxDynamicSharedMemorySize, SMEM_BYTES);
    cudaFuncSetAttribute(blend_mma<HID, LATD, false, true>,
                         cudaFuncAttributeMaxDynamicSharedMemorySize, SMEM_BYTES);

    blend_mma<NIN, HID, true, false><<<nsm, NTHREADS, SMEM_BYTES>>>(
        x, w1, b1, h1, nullptr);
    blend_mma<HID, HID, true, false><<<nsm, NTHREADS, SMEM_BYTES>>>(
        h1, w2, b2, h2, nullptr);
    blend_mma<HID, HID, true, false><<<nsm, NTHREADS, SMEM_BYTES>>>(
        h2, w3, b3, h1, nullptr);
    blend_mma<HID, LATD, false, true><<<nsm, NTHREADS, SMEM_BYTES>>>(
        h1, w4, b4, nullptr, out);
}

// round 16
// speedup vs baseline: 1.0287x; 1.0287x over previous
#include <cuda_runtime.h>
#include <cuda_bf16.h>
#include <cuda_fp16.h>
#include <math.h>
#include <stdint.h>

// Problem constants
#define B_ROWS 131072
#define FEAT 256
#define LATD 128
#define NIN 640           // 2*FEAT + LATD
#define HG 32
#define HID 512
#define NE 3

// ---------------------------------------------------------------------------
// Scratch (device globals — no runtime allocation allowed)
// ---------------------------------------------------------------------------
__device__ float g_gate[(size_t)B_ROWS * NE];

__device__ __half g_x[(size_t)B_ROWS * NIN];
__device__ __half g_h1[(size_t)B_ROWS * HID];
__device__ __half g_h2[(size_t)B_ROWS * HID];

__device__ __half g_w1[NE * HID * NIN];
__device__ __half g_w2[NE * HID * HID];
__device__ __half g_w3[NE * HID * HID];
__device__ __half g_w4[NE * LATD * HID];

// ---------------------------------------------------------------------------
// helpers
// ---------------------------------------------------------------------------
__device__ __forceinline__ uint32_t smem_u32(const void* p) {
    uint32_t a;
    asm("{ .reg .u64 t; cvta.to.shared.u64 t, %1; cvt.u32.u64 %0, t; }" : "=r"(a) : "l"(p));
    return a;
}

#define CP_ASYNC16(dst, src) \
    asm volatile("cp.async.cg.shared.global [%0], [%1], 16;" :: "r"(dst), "l"(src))
#define CP_COMMIT() asm volatile("cp.async.commit_group;" ::: "memory")
#define CP_WAIT0()  asm volatile("cp.async.wait_group 0;" ::: "memory")

__device__ __forceinline__ void mma16816h(float* c, const unsigned* a, const unsigned* b) {
    asm volatile(
        "mma.sync.aligned.m16n8k16.row.col.f32.f16.f16.f32 "
        "{%0,%1,%2,%3}, {%4,%5,%6,%7}, {%8,%9}, {%0,%1,%2,%3};\n"
        : "+f"(c[0]), "+f"(c[1]), "+f"(c[2]), "+f"(c[3])
        : "r"(a[0]), "r"(a[1]), "r"(a[2]), "r"(a[3]), "r"(b[0]), "r"(b[1]));
}

__device__ __forceinline__ unsigned lds32h(const __half* p) {
    return *reinterpret_cast<const unsigned*>(p);
}

// ---------------------------------------------------------------------------
// weight conversion — single launch for all four weight tensors
// ---------------------------------------------------------------------------
#define W1_N4 (NE * HID * NIN / 4)
#define W2_N4 (NE * HID * HID / 4)
#define W4_N4 (NE * LATD * HID / 4)
#define WTOT_N4 (W1_N4 + 2 * W2_N4 + W4_N4)

__global__ __launch_bounds__(256) void convert_all(
    const float* __restrict__ W1, const float* __restrict__ W2,
    const float* __restrict__ W3, const float* __restrict__ W4)
{
    int i = blockIdx.x * blockDim.x + threadIdx.x;
    if (i >= WTOT_N4) return;
    const float* src;
    __half* dst;
    int off;
    if (i < W1_N4)                    { src = W1; dst = g_w1; off = i; }
    else if (i < W1_N4 + W2_N4)       { src = W2; dst = g_w2; off = i - W1_N4; }
    else if (i < W1_N4 + 2 * W2_N4)   { src = W3; dst = g_w3; off = i - W1_N4 - W2_N4; }
    else                              { src = W4; dst = g_w4; off = i - W1_N4 - 2 * W2_N4; }
    float4 v = reinterpret_cast<const float4*>(src)[off];
    __half2* dp = reinterpret_cast<__half2*>(dst) + off * 2;
    dp[0] = __half2{__float2half_rn(v.x), __float2half_rn(v.y)};
    dp[1] = __half2{__float2half_rn(v.z), __float2half_rn(v.w)};
}

// ---------------------------------------------------------------------------
// fused prep: reads fp32 inputs ONCE; writes g_x (fp16) AND full gate path.
// ---------------------------------------------------------------------------
__global__ __launch_bounds__(256) void prep_gate_kernel(
    const float* __restrict__ f1, const float* __restrict__ f2,
    const float* __restrict__ lat,
    const float* __restrict__ g0w, const float* __restrict__ g0b,
    const float* __restrict__ g1w, const float* __restrict__ g1b,
    const float* __restrict__ g2w, const float* __restrict__ g2b,
    float* __restrict__ out_gate)
{
    __shared__ float As[16][260];
    __shared__ float Ws[16][36];
    __shared__ float us[256][33];
    __shared__ float w1s[32][33];
    __shared__ float b1s[32];
    __shared__ float w2s[3][32];
    __shared__ float b2s[3];

    const int tid = threadIdx.x;
    const int tx = tid & 7;
    const int ty = tid >> 3;
    const int m0 = blockIdx.x * 256;

    for (int idx = tid; idx < 32 * 32; idx += 256)
        w1s[idx >> 5][idx & 31] = g1w[idx];
    if (tid < 32) b1s[tid] = g1b[tid];
    if (tid < 96) w2s[tid / 32][tid % 32] = g2w[tid];
    if (tid < 3) b2s[tid] = g2b[tid];

    float acc[8][4];
#pragma unroll
    for (int i = 0; i < 8; ++i)
#pragma unroll
        for (int j = 0; j < 4; ++j) acc[i][j] = 0.f;

    for (int k0 = 0; k0 < NIN; k0 += 16) {
#pragma unroll
        for (int r = 0; r < 4; ++r) {
            int idx = r * 256 + tid;
            int m = idx >> 2;
            int kq = (idx & 3) * 4;
            int kg = k0 + kq;
            float4 v;
            if (kg < FEAT)
                v = *reinterpret_cast<const float4*>(&f1[(size_t)(m0 + m) * FEAT + kg]);
            else if (kg < 2 * FEAT)
                v = *reinterpret_cast<const float4*>(&f2[(size_t)(m0 + m) * FEAT + (kg - FEAT)]);
            else
                v = *reinterpret_cast<const float4*>(&lat[(size_t)(m0 + m) * LATD + (kg - 2 * FEAT)]);
            As[kq + 0][m] = v.x; As[kq + 1][m] = v.y;
            As[kq + 2][m] = v.z; As[kq + 3][m] = v.w;
            __half2 h01 = __half2{__float2half_rn(v.x), __float2half_rn(v.y)};
            __half2 h23 = __half2{__float2half_rn(v.z), __float2half_rn(v.w)};
            size_t xb = (size_t)(m0 + m) * NIN + kg;
            *reinterpret_cast<__half2*>(&g_x[xb])     = h01;
            *reinterpret_cast<__half2*>(&g_x[xb + 2]) = h23;
        }
        if (tid < 128) {
            int n = tid >> 2;
            int kq = (tid & 3) * 4;
            float4 v = *reinterpret_cast<const float4*>(&g0w[(size_t)n * NIN + k0 + kq]);
            Ws[kq + 0][n] = v.x; Ws[kq + 1][n] = v.y;
            Ws[kq + 2][n] = v.z; Ws[kq + 3][n] = v.w;
        }
        __syncthreads();
#pragma unroll
        for (int k = 0; k < 16; ++k) {
            const float4 a0 = *reinterpret_cast<const float4*>(&As[k][ty * 8]);
            const float4 a1 = *reinterpret_cast<const float4*>(&As[k][ty * 8 + 4]);
            const float4 b  = *reinterpret_cast<const float4*>(&Ws[k][tx * 4]);
            float av[8] = {a0.x, a0.y, a0.z, a0.w, a1.x, a1.y, a1.z, a1.w};
            float bv[4] = {b.x, b.y, b.z, b.w};
#pragma unroll
            for (int i = 0; i < 8; ++i)
#pragma unroll
                for (int j = 0; j < 4; ++j)
                    acc[i][j] = fmaf(av[i], bv[j], acc[i][j]);
        }
        __syncthreads();
    }

    float bb[4];
#pragma unroll
    for (int j = 0; j < 4; ++j) bb[j] = g0b[tx * 4 + j];
#pragma unroll
    for (int i = 0; i < 8; ++i)
#pragma unroll
        for (int j = 0; j < 4; ++j)
            us[ty * 8 + i][tx * 4 + j] = acc[i][j] + bb[j];
    __syncthreads();

    const int m = m0 + tid;

    float eu[32];
#pragma unroll
    for (int k = 0; k < 32; ++k) {
        float x = us[tid][k];
        eu[k] = (x > 0.f) ? x : expm1f(x);
    }
    float ev[32];
#pragma unroll
    for (int j = 0; j < 32; ++j) {
        float v = b1s[j];
#pragma unroll
        for (int k = 0; k < 32; ++k) v = fmaf(eu[k], w1s[j][k], v);
        ev[j] = (v > 0.f) ? v : expm1f(v);
    }
    float s[3];
#pragma unroll
    for (int e = 0; e < 3; ++e) {
        float v = b2s[e];
#pragma unroll
        for (int j = 0; j < 32; ++j) v = fmaf(ev[j], w2s[e][j], v);
        s[e] = v;
    }
    float mx = fmaxf(s[0], fmaxf(s[1], s[2]));
    float p0 = expf(s[0] - mx);
    float p1 = expf(s[1] - mx);
    float p2 = expf(s[2] - mx);
    float inv = 1.f / (p0 + p1 + p2);
    p0 *= inv; p1 *= inv; p2 *= inv;

    g_gate[(size_t)m * 3 + 0] = p0;
    g_gate[(size_t)m * 3 + 1] = p1;
    g_gate[(size_t)m * 3 + 2] = p2;
    out_gate[(size_t)m * 3 + 0] = p0;
    out_gate[(size_t)m * 3 + 1] = p1;
    out_gate[(size_t)m * 3 + 2] = p2;
}

// ---------------------------------------------------------------------------
// blend_mma v11 (= R13 + register-double-buffered A fragments):
// pure fp16 GEMM, persistent CTAs, K-chunk 128, 2-stage smem pipeline,
// ONE barrier per chunk, 1 CTA/SM, tile M=128 x N=64 x E=3, 8 warps.
// Inner loop: A fragments for kstep+1 are loaded into a second register set
// during kstep's expert-0 mma block, overlapping LDS latency with mma.
// ---------------------------------------------------------------------------
#define ASTRIDE 136
#define AROWS 128
#define WROWS 192
#define STAGE_U ((AROWS + WROWS) * ASTRIDE)   // 43520 half units

template <int KDIM, int NOUT>
__device__ __forceinline__ void prefetch_chunk(
    __half* sm, int stage, int k0, int m0, int n0,
    const __half* __restrict__ A, const __half* __restrict__ W)
{
    const int tid = threadIdx.x;
    const uint32_t base = smem_u32(sm) + (uint32_t)stage * STAGE_U * 2;
#pragma unroll
    for (int it = 0; it < 20; ++it) {
        int i = tid + it * 256;               // 0..5119
        uint32_t dst;
        const __half* src;
        if (i < 2048) {
            int row = i >> 4, c = i & 15;
            src = A + (size_t)(m0 + row) * KDIM + k0 + c * 8;
            dst = base + (uint32_t)(row * ASTRIDE + c * 8) * 2;
        } else {
            int j = i - 2048;                 // 0..3071
            int r = j >> 4, c = j & 15;       // r in [0,192)
            int e = r >> 6, n = r & 63;
            src = W + ((size_t)e * NOUT + n0 + n) * KDIM + k0 + c * 8;
            dst = base + (uint32_t)(AROWS * ASTRIDE + r * ASTRIDE + c * 8) * 2;
        }
        CP_ASYNC16(dst, src);
    }
}

template <int KDIM, int NOUT, bool RELU, bool FP32OUT>
__global__ __launch_bounds__(256, 1) void blend_mma(
    const __half* __restrict__ A, const __half* __restrict__ W,
    const float* __restrict__ bias,
    __half* __restrict__ Oh, float* __restrict__ Ofp)
{
    extern __shared__ __half smbuf[];

    constexpr int NTN = NOUT / 64;
    constexpr int NT = (B_ROWS / 128) * NTN;
    constexpr int NCH = KDIM / 128;

    const int tid = threadIdx.x;
    const int w = tid >> 5, lane = tid & 31;
    const int wm = w & 3, wn = w >> 2;        // warps: 4 along M, 2 along N
    const int g = lane >> 2, t = lane & 3;
    const int stride = gridDim.x;

    int tile = blockIdx.x;
    if (tile >= NT) return;

    {
        int m0 = (tile / NTN) * 128, n0 = (tile % NTN) * 64;
        prefetch_chunk<KDIM, NOUT>(smbuf, 0, 0, m0, n0, A, W);
        CP_COMMIT();
    }
    int gbuf = 0;

    // base offsets for this thread's A fragment rows (in half units, no k)
    const int arow0 = (wm * 32 + 0 * 16 + g) * ASTRIDE + t * 2;
    const int arow1 = (wm * 32 + 1 * 16 + g) * ASTRIDE + t * 2;

    while (tile < NT) {
        const int m0 = (tile / NTN) * 128;
        const int n0 = (tile % NTN) * 64;

        float gv[2][2][3];
#pragma unroll
        for (int mt = 0; mt < 2; ++mt)
#pragma unroll
            for (int h = 0; h < 2; ++h) {
                int m = m0 + wm * 32 + mt * 16 + g + h * 8;
                gv[mt][h][0] = g_gate[(size_t)m * 3 + 0];
                gv[mt][h][1] = g_gate[(size_t)m * 3 + 1];
                gv[mt][h][2] = g_gate[(size_t)m * 3 + 2];
            }
        float bb[3][4][2];
#pragma unroll
        for (int e = 0; e < 3; ++e)
#pragma unroll
            for (int nt = 0; nt < 4; ++nt) {
                int n = n0 + wn * 32 + nt * 8 + t * 2;
                bb[e][nt][0] = bias[e * NOUT + n];
                bb[e][nt][1] = bias[e * NOUT + n + 1];
            }

        float acc[3][2][4][4];
#pragma unroll
        for (int e = 0; e < 3; ++e)
#pragma unroll
            for (int mt = 0; mt < 2; ++mt)
#pragma unroll
                for (int nt = 0; nt < 4; ++nt)
#pragma unroll
                    for (int c = 0; c < 4; ++c) acc[e][mt][nt][c] = 0.f;

        for (int ch = 0; ch < NCH; ++ch) {
            CP_WAIT0();
            __syncthreads();

            {
                int pch = ch + 1, ptile = tile;
                if (pch >= NCH) { pch = 0; ptile += stride; }
                if (ptile < NT) {
                    int pm0 = (ptile / NTN) * 128, pn0 = (ptile % NTN) * 64;
                    prefetch_chunk<KDIM, NOUT>(smbuf, gbuf ^ 1, pch * 128,
                                               pm0, pn0, A, W);
                    CP_COMMIT();
                }
            }

            const __half* sA = smbuf + gbuf * STAGE_U;
            const __half* sW = sA + AROWS * ASTRIDE;

            // register double-buffer for A fragments
            unsigned acur[2][4], anxt[2][4];
            // load kstep 0
#pragma unroll
            for (int mt = 0; mt < 2; ++mt) {
                int r0 = (mt ? arow1 : arow0);
                acur[mt][0] = lds32h(sA + r0);
                acur[mt][1] = lds32h(sA + r0 + 8 * ASTRIDE);
                acur[mt][2] = lds32h(sA + r0 + 8);
                acur[mt][3] = lds32h(sA + r0 + 8 * ASTRIDE + 8);
            }

#pragma unroll
            for (int ks = 0; ks < 128; ks += 16) {
#pragma unroll
                for (int e = 0; e < 3; ++e) {
                    unsigned b[4][2];
#pragma unroll
                    for (int nt = 0; nt < 4; ++nt) {
                        int c0 = (e * 64 + wn * 32 + nt * 8 + g) * ASTRIDE + ks + t * 2;
                        b[nt][0] = lds32h(sW + c0);
                        b[nt][1] = lds32h(sW + c0 + 8);
                    }
                    if (e == 0 && ks + 16 < 128) {
                        // prefetch next kstep's A fragments into the other buffer
#pragma unroll
                        for (int mt = 0; mt < 2; ++mt) {
                            int r0 = (mt ? arow1 : arow0) + ks + 16;
                            anxt[mt][0] = lds32h(sA + r0);
                            anxt[mt][1] = lds32h(sA + r0 + 8 * ASTRIDE);
                            anxt[mt][2] = lds32h(sA + r0 + 8);
                            anxt[mt][3] = lds32h(sA + r0 + 8 * ASTRIDE + 8);
                        }
                    }
#pragma unroll
                    for (int mt = 0; mt < 2; ++mt)
#pragma unroll
                        for (int nt = 0; nt < 4; ++nt)
                            mma16816h(acc[e][mt][nt], acur[mt], b[nt]);
                }
                // rotate buffers
#pragma unroll
                for (int mt = 0; mt < 2; ++mt)
#pragma unroll
                    for (int q = 0; q < 4; ++q)
                        acur[mt][q] = anxt[mt][q];
            }
            gbuf ^= 1;
        }

        // ---------------- epilogue (register-only operands) ----------------
#pragma unroll
        for (int mt = 0; mt < 2; ++mt)
#pragma unroll
            for (int h = 0; h < 2; ++h) {
                int m = m0 + wm * 32 + mt * 16 + g + h * 8;
                float ga = gv[mt][h][0], gb = gv[mt][h][1], gc = gv[mt][h][2];
#pragma unroll
                for (int nt = 0; nt < 4; ++nt) {
                    int n = n0 + wn * 32 + nt * 8 + t * 2;
                    float v0 = ga * (acc[0][mt][nt][h * 2 + 0] + bb[0][nt][0])
                             + gb * (acc[1][mt][nt][h * 2 + 0] + bb[1][nt][0])
                             + gc * (acc[2][mt][nt][h * 2 + 0] + bb[2][nt][0]);
                    float v1 = ga * (acc[0][mt][nt][h * 2 + 1] + bb[0][nt][1])
                             + gb * (acc[1][mt][nt][h * 2 + 1] + bb[1][nt][1])
                             + gc * (acc[2][mt][nt][h * 2 + 1] + bb[2][nt][1]);
                    if (RELU) { v0 = fmaxf(v0, 0.f); v1 = fmaxf(v1, 0.f); }
                    if (FP32OUT) {
                        float2 o = {v0, v1};
                        *reinterpret_cast<float2*>(&Ofp[(size_t)m * NOUT + n]) = o;
                    } else {
                        *reinterpret_cast<__half2*>(&Oh[(size_t)m * NOUT + n]) =
                            __half2{__float2half_rn(v0), __float2half_rn(v1)};
                    }
                }
            }

        tile += stride;
    }
}

// ---------------------------------------------------------------------------
// Launch
// ---------------------------------------------------------------------------
extern "C" void kernel_launch(void* const* d_in, const int* in_sizes, int n_in,
                              void* d_out, int out_size)
{
    const float* f1  = (const float*)d_in[0];
    const float* f2  = (const float*)d_in[1];
    const float* lat = (const float*)d_in[2];
    const float* g0w = (const float*)d_in[3];
    const float* g0b = (const float*)d_in[4];
    const float* g1w = (const float*)d_in[5];
    const float* g1b = (const float*)d_in[6];
    const float* g2w = (const float*)d_in[7];
    const float* g2b = (const float*)d_in[8];
    const float* W1  = (const float*)d_in[9];
    const float* b1  = (const float*)d_in[10];
    const float* W2  = (const float*)d_in[11];
    const float* b2  = (const float*)d_in[12];
    const float* W3  = (const float*)d_in[13];
    const float* b3  = (const float*)d_in[14];
    const float* W4  = (const float*)d_in[15];
    const float* b4  = (const float*)d_in[16];

    float* out      = (float*)d_out;
    float* gate_out = out + (size_t)B_ROWS * LATD;

    __half *w1, *w2, *w3, *w4, *x, *h1, *h2;
    cudaGetSymbolAddress((void**)&w1, g_w1);
    cudaGetSymbolAddress((void**)&w2, g_w2);
    cudaGetSymbolAddress((void**)&w3, g_w3);
    cudaGetSymbolAddress((void**)&w4, g_w4);
    cudaGetSymbolAddress((void**)&x,  g_x);
    cudaGetSymbolAddress((void**)&h1, g_h1);
    cudaGetSymbolAddress((void**)&h2, g_h2);

    int nsm = 148;
    cudaDeviceGetAttribute(&nsm, cudaDevAttrMultiProcessorCount, 0);

    // single-launch weight conversion
    convert_all<<<(WTOT_N4 + 255) / 256, 256>>>(W1, W2, W3, W4);

    // fused prep: inputs -> g_x + full gate path
    prep_gate_kernel<<<B_ROWS / 256, 256>>>(f1, f2, lat, g0w, g0b,
                                            g1w, g1b, g2w, g2b, gate_out);

    // blend layers — persistent grid, dynamic smem (2 stages of 87040B)
    constexpr int SMEM_BYTES = 2 * STAGE_U * 2;   // 174080

    cudaFuncSetAttribute(blend_mma<NIN, HID, true, false>,
                         cudaFuncAttributeMaxDynamicSharedMemorySize, SMEM_BYTES);
    cudaFuncSetAttribute(blend_mma<HID, HID, true, false>,
                         cudaFuncAttributeMaxDynamicSharedMemorySize, SMEM_BYTES);
    cudaFuncSetAttribute(blend_mma<HID, LATD, false, true>,
                         cudaFuncAttributeMaxDynamicSharedMemorySize, SMEM_BYTES);

    blend_mma<NIN, HID, true, false><<<nsm, 256, SMEM_BYTES>>>(
        x, w1, b1, h1, nullptr);
    blend_mma<HID, HID, true, false><<<nsm, 256, SMEM_BYTES>>>(
        h1, w2, b2, h2, nullptr);
    blend_mma<HID, HID, true, false><<<nsm, 256, SMEM_BYTES>>>(
        h2, w3, b3, h1, nullptr);
    blend_mma<HID, LATD, false, true><<<nsm, 256, SMEM_BYTES>>>(
        h1, w4, b4, nullptr, out);
}

// round 17
// speedup vs baseline: 1.0411x; 1.0121x over previous
#include <cuda_runtime.h>
#include <cuda_bf16.h>
#include <cuda_fp16.h>
#include <math.h>
#include <stdint.h>

// Problem constants
#define B_ROWS 131072
#define FEAT 256
#define LATD 128
#define NIN 640           // 2*FEAT + LATD
#define HG 32
#define HID 512
#define NE 3

// ---------------------------------------------------------------------------
// Scratch (device globals — no runtime allocation allowed)
// ---------------------------------------------------------------------------
__device__ float g_gate[(size_t)B_ROWS * NE];

__device__ __half g_x[(size_t)B_ROWS * NIN];
__device__ __half g_h1[(size_t)B_ROWS * HID];
__device__ __half g_h2[(size_t)B_ROWS * HID];

__device__ __half g_w1[NE * HID * NIN];
__device__ __half g_w2[NE * HID * HID];
__device__ __half g_w3[NE * HID * HID];
__device__ __half g_w4[NE * LATD * HID];

// ---------------------------------------------------------------------------
// helpers
// ---------------------------------------------------------------------------
__device__ __forceinline__ uint32_t smem_u32(const void* p) {
    uint32_t a;
    asm("{ .reg .u64 t; cvta.to.shared.u64 t, %1; cvt.u32.u64 %0, t; }" : "=r"(a) : "l"(p));
    return a;
}

#define CP_ASYNC16(dst, src) \
    asm volatile("cp.async.cg.shared.global [%0], [%1], 16;" :: "r"(dst), "l"(src))
#define CP_COMMIT() asm volatile("cp.async.commit_group;" ::: "memory")
#define CP_WAIT0()  asm volatile("cp.async.wait_group 0;" ::: "memory")

__device__ __forceinline__ void mma16816h(float* c, const unsigned* a, const unsigned* b) {
    asm volatile(
        "mma.sync.aligned.m16n8k16.row.col.f32.f16.f16.f32 "
        "{%0,%1,%2,%3}, {%4,%5,%6,%7}, {%8,%9}, {%0,%1,%2,%3};\n"
        : "+f"(c[0]), "+f"(c[1]), "+f"(c[2]), "+f"(c[3])
        : "r"(a[0]), "r"(a[1]), "r"(a[2]), "r"(a[3]), "r"(b[0]), "r"(b[1]));
}

__device__ __forceinline__ unsigned lds32h(const __half* p) {
    return *reinterpret_cast<const unsigned*>(p);
}

// ---------------------------------------------------------------------------
// weight conversion — single launch for all four weight tensors
// ---------------------------------------------------------------------------
#define W1_N4 (NE * HID * NIN / 4)
#define W2_N4 (NE * HID * HID / 4)
#define W4_N4 (NE * LATD * HID / 4)
#define WTOT_N4 (W1_N4 + 2 * W2_N4 + W4_N4)

__global__ __launch_bounds__(256) void convert_all(
    const float* __restrict__ W1, const float* __restrict__ W2,
    const float* __restrict__ W3, const float* __restrict__ W4)
{
    int i = blockIdx.x * blockDim.x + threadIdx.x;
    if (i >= WTOT_N4) return;
    const float* src;
    __half* dst;
    int off;
    if (i < W1_N4)                    { src = W1; dst = g_w1; off = i; }
    else if (i < W1_N4 + W2_N4)       { src = W2; dst = g_w2; off = i - W1_N4; }
    else if (i < W1_N4 + 2 * W2_N4)   { src = W3; dst = g_w3; off = i - W1_N4 - W2_N4; }
    else                              { src = W4; dst = g_w4; off = i - W1_N4 - 2 * W2_N4; }
    float4 v = reinterpret_cast<const float4*>(src)[off];
    __half2* dp = reinterpret_cast<__half2*>(dst) + off * 2;
    dp[0] = __half2{__float2half_rn(v.x), __float2half_rn(v.y)};
    dp[1] = __half2{__float2half_rn(v.z), __float2half_rn(v.w)};
}

// ---------------------------------------------------------------------------
// fused prep: reads fp32 inputs ONCE; writes g_x (fp16) AND full gate path.
// ---------------------------------------------------------------------------
__global__ __launch_bounds__(256) void prep_gate_kernel(
    const float* __restrict__ f1, const float* __restrict__ f2,
    const float* __restrict__ lat,
    const float* __restrict__ g0w, const float* __restrict__ g0b,
    const float* __restrict__ g1w, const float* __restrict__ g1b,
    const float* __restrict__ g2w, const float* __restrict__ g2b,
    float* __restrict__ out_gate)
{
    __shared__ float As[16][260];
    __shared__ float Ws[16][36];
    __shared__ float us[256][33];
    __shared__ float w1s[32][33];
    __shared__ float b1s[32];
    __shared__ float w2s[3][32];
    __shared__ float b2s[3];

    const int tid = threadIdx.x;
    const int tx = tid & 7;
    const int ty = tid >> 3;
    const int m0 = blockIdx.x * 256;

    for (int idx = tid; idx < 32 * 32; idx += 256)
        w1s[idx >> 5][idx & 31] = g1w[idx];
    if (tid < 32) b1s[tid] = g1b[tid];
    if (tid < 96) w2s[tid / 32][tid % 32] = g2w[tid];
    if (tid < 3) b2s[tid] = g2b[tid];

    float acc[8][4];
#pragma unroll
    for (int i = 0; i < 8; ++i)
#pragma unroll
        for (int j = 0; j < 4; ++j) acc[i][j] = 0.f;

    for (int k0 = 0; k0 < NIN; k0 += 16) {
#pragma unroll
        for (int r = 0; r < 4; ++r) {
            int idx = r * 256 + tid;
            int m = idx >> 2;
            int kq = (idx & 3) * 4;
            int kg = k0 + kq;
            float4 v;
            if (kg < FEAT)
                v = *reinterpret_cast<const float4*>(&f1[(size_t)(m0 + m) * FEAT + kg]);
            else if (kg < 2 * FEAT)
                v = *reinterpret_cast<const float4*>(&f2[(size_t)(m0 + m) * FEAT + (kg - FEAT)]);
            else
                v = *reinterpret_cast<const float4*>(&lat[(size_t)(m0 + m) * LATD + (kg - 2 * FEAT)]);
            As[kq + 0][m] = v.x; As[kq + 1][m] = v.y;
            As[kq + 2][m] = v.z; As[kq + 3][m] = v.w;
            __half2 h01 = __half2{__float2half_rn(v.x), __float2half_rn(v.y)};
            __half2 h23 = __half2{__float2half_rn(v.z), __float2half_rn(v.w)};
            size_t xb = (size_t)(m0 + m) * NIN + kg;
            *reinterpret_cast<__half2*>(&g_x[xb])     = h01;
            *reinterpret_cast<__half2*>(&g_x[xb + 2]) = h23;
        }
        if (tid < 128) {
            int n = tid >> 2;
            int kq = (tid & 3) * 4;
            float4 v = *reinterpret_cast<const float4*>(&g0w[(size_t)n * NIN + k0 + kq]);
            Ws[kq + 0][n] = v.x; Ws[kq + 1][n] = v.y;
            Ws[kq + 2][n] = v.z; Ws[kq + 3][n] = v.w;
        }
        __syncthreads();
#pragma unroll
        for (int k = 0; k < 16; ++k) {
            const float4 a0 = *reinterpret_cast<const float4*>(&As[k][ty * 8]);
            const float4 a1 = *reinterpret_cast<const float4*>(&As[k][ty * 8 + 4]);
            const float4 b  = *reinterpret_cast<const float4*>(&Ws[k][tx * 4]);
            float av[8] = {a0.x, a0.y, a0.z, a0.w, a1.x, a1.y, a1.z, a1.w};
            float bv[4] = {b.x, b.y, b.z, b.w};
#pragma unroll
            for (int i = 0; i < 8; ++i)
#pragma unroll
                for (int j = 0; j < 4; ++j)
                    acc[i][j] = fmaf(av[i], bv[j], acc[i][j]);
        }
        __syncthreads();
    }

    float bb[4];
#pragma unroll
    for (int j = 0; j < 4; ++j) bb[j] = g0b[tx * 4 + j];
#pragma unroll
    for (int i = 0; i < 8; ++i)
#pragma unroll
        for (int j = 0; j < 4; ++j)
            us[ty * 8 + i][tx * 4 + j] = acc[i][j] + bb[j];
    __syncthreads();

    const int m = m0 + tid;

    float eu[32];
#pragma unroll
    for (int k = 0; k < 32; ++k) {
        float x = us[tid][k];
        eu[k] = (x > 0.f) ? x : expm1f(x);
    }
    float ev[32];
#pragma unroll
    for (int j = 0; j < 32; ++j) {
        float v = b1s[j];
#pragma unroll
        for (int k = 0; k < 32; ++k) v = fmaf(eu[k], w1s[j][k], v);
        ev[j] = (v > 0.f) ? v : expm1f(v);
    }
    float s[3];
#pragma unroll
    for (int e = 0; e < 3; ++e) {
        float v = b2s[e];
#pragma unroll
        for (int j = 0; j < 32; ++j) v = fmaf(ev[j], w2s[e][j], v);
        s[e] = v;
    }
    float mx = fmaxf(s[0], fmaxf(s[1], s[2]));
    float p0 = expf(s[0] - mx);
    float p1 = expf(s[1] - mx);
    float p2 = expf(s[2] - mx);
    float inv = 1.f / (p0 + p1 + p2);
    p0 *= inv; p1 *= inv; p2 *= inv;

    g_gate[(size_t)m * 3 + 0] = p0;
    g_gate[(size_t)m * 3 + 1] = p1;
    g_gate[(size_t)m * 3 + 2] = p2;
    out_gate[(size_t)m * 3 + 0] = p0;
    out_gate[(size_t)m * 3 + 1] = p1;
    out_gate[(size_t)m * 3 + 2] = p2;
}

// ---------------------------------------------------------------------------
// blend_mma v12 (= R13 + n-outer tile order + W-resident smem elision):
// pure fp16 GEMM, persistent CTAs, K-chunk 128, 2-stage smem pipeline,
// ONE barrier per chunk, 1 CTA/SM, tile M=128 x N=64 x E=3, 8 warps.
// Tile order n-outer: consecutive tiles of a CTA share n0, so the W region
// of a buffer is still valid when its (n0,k0) tag matches -> A-only prefetch.
// ---------------------------------------------------------------------------
#define ASTRIDE 136
#define AROWS 128
#define WROWS 192
#define STAGE_U ((AROWS + WROWS) * ASTRIDE)   // 43520 half units

template <int KDIM, int NOUT>
__device__ __forceinline__ void prefetch_chunk(
    __half* sm, int stage, int k0, int m0, int n0, bool loadW,
    const __half* __restrict__ A, const __half* __restrict__ W)
{
    const int tid = threadIdx.x;
    const uint32_t base = smem_u32(sm) + (uint32_t)stage * STAGE_U * 2;
    // A region: 128 rows * 16 = 2048 16B-chunks (always)
#pragma unroll
    for (int it = 0; it < 8; ++it) {
        int i = tid + it * 256;               // 0..2047
        int row = i >> 4, c = i & 15;
        const __half* src = A + (size_t)(m0 + row) * KDIM + k0 + c * 8;
        uint32_t dst = base + (uint32_t)(row * ASTRIDE + c * 8) * 2;
        CP_ASYNC16(dst, src);
    }
    // W region: 192 rows * 16 = 3072 16B-chunks (only when tag miss)
    if (loadW) {
#pragma unroll
        for (int it = 0; it < 12; ++it) {
            int j = tid + it * 256;           // 0..3071
            int r = j >> 4, c = j & 15;       // r in [0,192)
            int e = r >> 6, n = r & 63;
            const __half* src = W + ((size_t)e * NOUT + n0 + n) * KDIM + k0 + c * 8;
            uint32_t dst = base + (uint32_t)(AROWS * ASTRIDE + r * ASTRIDE + c * 8) * 2;
            CP_ASYNC16(dst, src);
        }
    }
}

template <int KDIM, int NOUT, bool RELU, bool FP32OUT>
__global__ __launch_bounds__(256, 1) void blend_mma(
    const __half* __restrict__ A, const __half* __restrict__ W,
    const float* __restrict__ bias,
    __half* __restrict__ Oh, float* __restrict__ Ofp)
{
    extern __shared__ __half smbuf[];

    constexpr int NTN = NOUT / 64;
    constexpr int NTM = B_ROWS / 128;
    constexpr int NT = NTM * NTN;
    constexpr int NCH = KDIM / 128;

    const int tid = threadIdx.x;
    const int w = tid >> 5, lane = tid & 31;
    const int wm = w & 3, wn = w >> 2;        // warps: 4 along M, 2 along N
    const int g = lane >> 2, t = lane & 3;
    const int stride = gridDim.x;

    int tile = blockIdx.x;
    if (tile >= NT) return;

    // per-buffer (n0,k0) tags for the W region (uniform across threads)
    int tagN[2] = {-1, -1}, tagK[2] = {-1, -1};

    {
        // n-outer order: m0 = (tile % NTM)*128, n0 = (tile / NTM)*64
        int m0 = (tile % NTM) * 128, n0 = (tile / NTM) * 64;
        prefetch_chunk<KDIM, NOUT>(smbuf, 0, 0, m0, n0, true, A, W);
        CP_COMMIT();
        tagN[0] = n0; tagK[0] = 0;
    }
    int gbuf = 0;

    while (tile < NT) {
        const int m0 = (tile % NTM) * 128;
        const int n0 = (tile / NTM) * 64;

        float gv[2][2][3];
#pragma unroll
        for (int mt = 0; mt < 2; ++mt)
#pragma unroll
            for (int h = 0; h < 2; ++h) {
                int m = m0 + wm * 32 + mt * 16 + g + h * 8;
                gv[mt][h][0] = g_gate[(size_t)m * 3 + 0];
                gv[mt][h][1] = g_gate[(size_t)m * 3 + 1];
                gv[mt][h][2] = g_gate[(size_t)m * 3 + 2];
            }
        float bb[3][4][2];
#pragma unroll
        for (int e = 0; e < 3; ++e)
#pragma unroll
            for (int nt = 0; nt < 4; ++nt) {
                int n = n0 + wn * 32 + nt * 8 + t * 2;
                bb[e][nt][0] = bias[e * NOUT + n];
                bb[e][nt][1] = bias[e * NOUT + n + 1];
            }

        float acc[3][2][4][4];
#pragma unroll
        for (int e = 0; e < 3; ++e)
#pragma unroll
            for (int mt = 0; mt < 2; ++mt)
#pragma unroll
                for (int nt = 0; nt < 4; ++nt)
#pragma unroll
                    for (int c = 0; c < 4; ++c) acc[e][mt][nt][c] = 0.f;

        for (int ch = 0; ch < NCH; ++ch) {
            CP_WAIT0();
            __syncthreads();

            {
                int pch = ch + 1, ptile = tile;
                if (pch >= NCH) { pch = 0; ptile += stride; }
                if (ptile < NT) {
                    int pm0 = (ptile % NTM) * 128, pn0 = (ptile / NTM) * 64;
                    int pk0 = pch * 128;
                    int b = gbuf ^ 1;
                    bool lw = !(tagN[b] == pn0 && tagK[b] == pk0);
                    prefetch_chunk<KDIM, NOUT>(smbuf, b, pk0, pm0, pn0, lw, A, W);
                    CP_COMMIT();
                    tagN[b] = pn0; tagK[b] = pk0;
                }
            }

            const __half* sA = smbuf + gbuf * STAGE_U;
            const __half* sW = sA + AROWS * ASTRIDE;

#pragma unroll
            for (int ks = 0; ks < 128; ks += 16) {
                unsigned a[2][4];
#pragma unroll
                for (int mt = 0; mt < 2; ++mt) {
                    int r0 = (wm * 32 + mt * 16 + g) * ASTRIDE + ks + t * 2;
                    int r1 = r0 + 8 * ASTRIDE;
                    a[mt][0] = lds32h(sA + r0);
                    a[mt][1] = lds32h(sA + r1);
                    a[mt][2] = lds32h(sA + r0 + 8);
                    a[mt][3] = lds32h(sA + r1 + 8);
                }
#pragma unroll
                for (int e = 0; e < 3; ++e) {
                    unsigned b[4][2];
#pragma unroll
                    for (int nt = 0; nt < 4; ++nt) {
                        int c0 = (e * 64 + wn * 32 + nt * 8 + g) * ASTRIDE + ks + t * 2;
                        b[nt][0] = lds32h(sW + c0);
                        b[nt][1] = lds32h(sW + c0 + 8);
                    }
#pragma unroll
                    for (int mt = 0; mt < 2; ++mt)
#pragma unroll
                        for (int nt = 0; nt < 4; ++nt)
                            mma16816h(acc[e][mt][nt], a[mt], b[nt]);
                }
            }
            gbuf ^= 1;
        }

        // ---------------- epilogue (register-only operands) ----------------
#pragma unroll
        for (int mt = 0; mt < 2; ++mt)
#pragma unroll
            for (int h = 0; h < 2; ++h) {
                int m = m0 + wm * 32 + mt * 16 + g + h * 8;
                float ga = gv[mt][h][0], gb = gv[mt][h][1], gc = gv[mt][h][2];
#pragma unroll
                for (int nt = 0; nt < 4; ++nt) {
                    int n = n0 + wn * 32 + nt * 8 + t * 2;
                    float v0 = ga * (acc[0][mt][nt][h * 2 + 0] + bb[0][nt][0])
                             + gb * (acc[1][mt][nt][h * 2 + 0] + bb[1][nt][0])
                             + gc * (acc[2][mt][nt][h * 2 + 0] + bb[2][nt][0]);
                    float v1 = ga * (acc[0][mt][nt][h * 2 + 1] + bb[0][nt][1])
                             + gb * (acc[1][mt][nt][h * 2 + 1] + bb[1][nt][1])
                             + gc * (acc[2][mt][nt][h * 2 + 1] + bb[2][nt][1]);
                    if (RELU) { v0 = fmaxf(v0, 0.f); v1 = fmaxf(v1, 0.f); }
                    if (FP32OUT) {
                        float2 o = {v0, v1};
                        *reinterpret_cast<float2*>(&Ofp[(size_t)m * NOUT + n]) = o;
                    } else {
                        *reinterpret_cast<__half2*>(&Oh[(size_t)m * NOUT + n]) =
                            __half2{__float2half_rn(v0), __float2half_rn(v1)};
                    }
                }
            }

        tile += stride;
    }
}

// ---------------------------------------------------------------------------
// Launch
// ---------------------------------------------------------------------------
extern "C" void kernel_launch(void* const* d_in, const int* in_sizes, int n_in,
                              void* d_out, int out_size)
{
    const float* f1  = (const float*)d_in[0];
    const float* f2  = (const float*)d_in[1];
    const float* lat = (const float*)d_in[2];
    const float* g0w = (const float*)d_in[3];
    const float* g0b = (const float*)d_in[4];
    const float* g1w = (const float*)d_in[5];
    const float* g1b = (const float*)d_in[6];
    const float* g2w = (const float*)d_in[7];
    const float* g2b = (const float*)d_in[8];
    const float* W1  = (const float*)d_in[9];
    const float* b1  = (const float*)d_in[10];
    const float* W2  = (const float*)d_in[11];
    const float* b2  = (const float*)d_in[12];
    const float* W3  = (const float*)d_in[13];
    const float* b3  = (const float*)d_in[14];
    const float* W4  = (const float*)d_in[15];
    const float* b4  = (const float*)d_in[16];

    float* out      = (float*)d_out;
    float* gate_out = out + (size_t)B_ROWS * LATD;

    __half *w1, *w2, *w3, *w4, *x, *h1, *h2;
    cudaGetSymbolAddress((void**)&w1, g_w1);
    cudaGetSymbolAddress((void**)&w2, g_w2);
    cudaGetSymbolAddress((void**)&w3, g_w3);
    cudaGetSymbolAddress((void**)&w4, g_w4);
    cudaGetSymbolAddress((void**)&x,  g_x);
    cudaGetSymbolAddress((void**)&h1, g_h1);
    cudaGetSymbolAddress((void**)&h2, g_h2);

    int nsm = 148;
    cudaDeviceGetAttribute(&nsm, cudaDevAttrMultiProcessorCount, 0);

    // single-launch weight conversion
    convert_all<<<(WTOT_N4 + 255) / 256, 256>>>(W1, W2, W3, W4);

    // fused prep: inputs -> g_x + full gate path
    prep_gate_kernel<<<B_ROWS / 256, 256>>>(f1, f2, lat, g0w, g0b,
                                            g1w, g1b, g2w, g2b, gate_out);

    // blend layers — persistent grid, dynamic smem (2 stages of 87040B)
    constexpr int SMEM_BYTES = 2 * STAGE_U * 2;   // 174080

    cudaFuncSetAttribute(blend_mma<NIN, HID, true, false>,
                         cudaFuncAttributeMaxDynamicSharedMemorySize, SMEM_BYTES);
    cudaFuncSetAttribute(blend_mma<HID, HID, true, false>,
                         cudaFuncAttributeMaxDynamicSharedMemorySize, SMEM_BYTES);
    cudaFuncSetAttribute(blend_mma<HID, LATD, false, true>,
                         cudaFuncAttributeMaxDynamicSharedMemorySize, SMEM_BYTES);

    blend_mma<NIN, HID, true, false><<<nsm, 256, SMEM_BYTES>>>(
        x, w1, b1, h1, nullptr);
    blend_mma<HID, HID, true, false><<<nsm, 256, SMEM_BYTES>>>(
        h1, w2, b2, h2, nullptr);
    blend_mma<HID, HID, true, false><<<nsm, 256, SMEM_BYTES>>>(
        h2, w3, b3, h1, nullptr);
    blend_mma<HID, LATD, false, true><<<nsm, 256, SMEM_BYTES>>>(
        h1, w4, b4, nullptr, out);
}